// round 7
// baseline (speedup 1.0000x reference)
#include <cuda_runtime.h>
#include <cstdint>

// Problem constants
#define BNUM   1024
#define QNUM   96
#define CNUM   16
#define HNUM   100
#define NSTEPS_K 100
#define QP1    97
#define ROWS   (BNUM*CNUM)   // 16384 rows
#define MT     128           // rows per CTA
#define NTHREADS 256         // 16 ty x 16 tx
#define RM     8
#define RN     7
#define NBLK   25            // K=100 in 4-k blocks

typedef unsigned int       u32t;
typedef unsigned long long u64t;

// Activation layout: row-major, 100 floats/row, +16B stagger per 8-row group:
//   float index(row, k) = row*100 + (row>>3)*4 + k
#define XROWF(row) ((row)*100 + ((row)>>3)*4)
#define SZ_ACT 12860

// Weight layout: j-major, uniform stride 108 (banks tx*12 mod 32 -> conflict-free
// 16B loads, monotone, no overlap). k=0..99 weights; k=100..103 pack W1t/b1/b2/b3.
#define WSTR   108
#define SZ_W12 (HNUM*WSTR)    // 10800
#define SZ_W3  (QP1*WSTR)     // 10476

// Shared memory layout (float offsets)
#define OFF_XS   0
#define OFF_HS   (OFF_XS + SZ_ACT)      // 12860
#define OFF_W1   (OFF_HS + SZ_ACT)      // 25720
#define OFF_W2   (OFF_W1 + SZ_W12)      // 36520
#define OFF_W3   (OFF_W2 + SZ_W12)      // 47320
#define SMEM_FLOATS (OFF_W3 + SZ_W3)    // 57796
#define SMEM_BYTES  (SMEM_FLOATS * 4)   // 231184 B (fits 227KB opt-in)

// packed extras inside each weight column (k-slot)
#define K_W1T 100   // W1[:,97] (t column)   [in W1 region]
#define K_B1  101   //                        [in W1 region]
#define K_B2  100   //                        [in W2 region]
#define K_B3  100   //                        [in W3 region]

extern __shared__ float smem[];

__device__ __forceinline__ void fma2(u64t& d, u64t a, u64t b) {
    asm("fma.rn.f32x2 %0, %1, %2, %0;" : "+l"(d) : "l"(a), "l"(b));
}
__device__ __forceinline__ u64t pack2(float lo, float hi) {
    u64t r;
    asm("mov.b64 %0, {%1, %2};" : "=l"(r) : "f"(lo), "f"(hi));
    return r;
}
__device__ __forceinline__ void unpack2(u64t v, float& lo, float& hi) {
    asm("mov.b64 {%0, %1}, %2;" : "=f"(lo), "=f"(hi) : "l"(v));
}
__device__ __forceinline__ float tanh_fast(float x) {
    asm("tanh.approx.f32 %0, %0;" : "+f"(x));
    return x;
}
__device__ __forceinline__ void lds_v2u64(u32t addr, u64t& a, u64t& b) {
    asm("ld.shared.v2.b64 {%0, %1}, [%2];" : "=l"(a), "=l"(b) : "r"(addr));
}
__device__ __forceinline__ float lds_f32(u32t addr) {
    float v;
    asm("ld.shared.f32 %0, [%1];" : "=f"(v) : "r"(addr));
    return v;
}
__device__ __forceinline__ void sts_f32(u32t addr, float v) {
    asm volatile("st.shared.f32 [%0], %1;" :: "r"(addr), "f"(v));
}

// GEMM tile: acc[r][i] (u64: even-k partial, odd-k partial) +=
//            A[row0+r][k-pairs] * W[col_i][k-pairs], K=100 (25 4-k blocks)
__device__ __forceinline__ void gemm_tile(u32t abase, u32t wbase,
                                          const u32t (&wof)[RN],
                                          u64t (&acc)[RM][RN])
{
    u32t ka = abase;
    u32t kw = wbase;
    #pragma unroll 1
    for (int blk = 0; blk < NBLK; blk++, ka += 16, kw += 16) {
        u64t w0[RN], w1[RN];
        #pragma unroll
        for (int i = 0; i < RN; i++)
            lds_v2u64(kw + wof[i], w0[i], w1[i]);
        #pragma unroll
        for (int r = 0; r < RM; r++) {
            u64t a0, a1;
            lds_v2u64(ka + r * 400, a0, a1);
            #pragma unroll
            for (int i = 0; i < RN; i++) fma2(acc[r][i], a0, w0[i]);
            #pragma unroll
            for (int i = 0; i < RN; i++) fma2(acc[r][i], a1, w1[i]);
        }
    }
}

__global__ __launch_bounds__(NTHREADS, 1)
void arima_flow_kernel(const float* __restrict__ series,
                       const float* __restrict__ rand_error,
                       const float* __restrict__ W1, const float* __restrict__ b1,
                       const float* __restrict__ W2, const float* __restrict__ b2,
                       const float* __restrict__ W3, const float* __restrict__ b3,
                       float* __restrict__ out)
{
    float* Xs  = smem + OFF_XS;
    float* W1s = smem + OFF_W1;
    float* W2s = smem + OFF_W2;
    float* W3s = smem + OFF_W3;

    u32t sb;
    asm("{ .reg .u64 t; cvta.to.shared.u64 t, %1; cvt.u32.u64 %0, t; }"
        : "=r"(sb) : "l"(smem));
    const u32t XS_U = sb + OFF_XS * 4;
    const u32t HS_U = sb + OFF_HS * 4;
    const u32t W1_U = sb + OFF_W1 * 4;
    const u32t W2_U = sb + OFF_W2 * 4;
    const u32t W3_U = sb + OFF_W3 * 4;

    const int tid  = threadIdx.x;
    const int tx   = tid & 15;
    const int ty   = tid >> 4;
    const int row0 = ty * RM;
    const int base = blockIdx.x * MT;

    // ---- zero all smem (padding correctness: X rows k=97..99, W k=97..99) ----
    for (int idx = tid; idx < SMEM_FLOATS; idx += NTHREADS) smem[idx] = 0.0f;
    __syncthreads();

    // ---- load weights (j-major, stride 108; extras packed at k>=100) ----
    for (int idx = tid; idx < HNUM * QP1; idx += NTHREADS) {
        int j = idx / QP1, k = idx - j * QP1;
        W1s[j * WSTR + k] = W1[j * (QNUM + 2) + k];
    }
    for (int j = tid; j < HNUM; j += NTHREADS) {
        W1s[j * WSTR + K_W1T] = W1[j * (QNUM + 2) + (QNUM + 1)];
        W1s[j * WSTR + K_B1]  = b1[j];
        W2s[j * WSTR + K_B2]  = b2[j];
    }
    for (int idx = tid; idx < HNUM * HNUM; idx += NTHREADS) {
        int j = idx / HNUM, k = idx - j * HNUM;
        W2s[j * WSTR + k] = W2[idx];
    }
    for (int idx = tid; idx < QP1 * HNUM; idx += NTHREADS) {
        int j = idx / HNUM, k = idx - j * HNUM;
        W3s[j * WSTR + k] = W3[idx];
    }
    for (int j = tid; j < QP1; j += NTHREADS) W3s[j * WSTR + K_B3] = b3[j];

    // ---- x0 = cat(series, rand_error), row-major staggered ----
    for (int idx = tid; idx < QP1 * MT; idx += NTHREADS) {
        int q = idx / MT, m = idx - q * MT;
        int row = base + m;
        int b = row >> 4, c = row & 15;
        float v = (q < QNUM) ? series[(b * QNUM + q) * CNUM + c]
                             : rand_error[b * CNUM + c];
        Xs[XROWF(m) + q] = v;
    }
    __syncthreads();

    // ---- per-thread constants ----
    int colh[RN], colq[RN];
    bool vh[RN], vq[RN];
    u32t wofh[RN], wofq[RN];
    #pragma unroll
    for (int i = 0; i < RN; i++) {
        int j = i * 16 + tx;
        vh[i] = (j < HNUM); colh[i] = vh[i] ? j : 0;
        vq[i] = (j < QP1);  colq[i] = vq[i] ? j : 0;
        wofh[i] = (u32t)(colh[i] * WSTR) * 4;
        wofq[i] = (u32t)(colq[i] * WSTR) * 4;
    }
    const u32t ABX = XS_U + (u32t)XROWF(row0) * 4;
    const u32t ABH = HS_U + (u32t)XROWF(row0) * 4;
    // global index helpers for noise reload
    int rb[RM], rc[RM];
    #pragma unroll
    for (int r = 0; r < RM; r++) {
        int row = base + row0 + r;
        rb[r] = row >> 4;
        rc[r] = row & 15;
    }

    const float dt = 1.0f / (float)NSTEPS_K;
    u64t acc[RM][RN];

    for (int s = 0; s < NSTEPS_K; s++) {
        const float t = (float)s / (float)NSTEPS_K;
        __syncthreads();  // [A] Xs stable, Hs free

        // ===== Layer 1: h1 = tanh(X @ W1^T + b1 + t*W1t) =====
        #pragma unroll
        for (int i = 0; i < RN; i++) {
            float w1t = lds_f32(W1_U + wofh[i] + K_W1T * 4);
            float bb  = lds_f32(W1_U + wofh[i] + K_B1 * 4);
            u64t b2 = pack2(fmaf(t, w1t, bb), 0.0f);
            #pragma unroll
            for (int r = 0; r < RM; r++) acc[r][i] = b2;
        }
        gemm_tile(ABX, W1_U, wofh, acc);
        #pragma unroll
        for (int i = 0; i < RN; i++) {
            if (vh[i]) {
                #pragma unroll
                for (int r = 0; r < RM; r++) {
                    float lo, hi; unpack2(acc[r][i], lo, hi);
                    sts_f32(ABH + r * 400 + colh[i] * 4, tanh_fast(lo + hi));
                }
            }
        }
        __syncthreads();  // [B] h1 visible

        // ===== Layer 2: h2 = tanh(h1 @ W2^T + b2) =====
        #pragma unroll
        for (int i = 0; i < RN; i++) {
            u64t b2 = pack2(lds_f32(W2_U + wofh[i] + K_B2 * 4), 0.0f);
            #pragma unroll
            for (int r = 0; r < RM; r++) acc[r][i] = b2;
        }
        gemm_tile(ABH, W2_U, wofh, acc);
        float h2[RM][RN];
        #pragma unroll
        for (int i = 0; i < RN; i++)
            #pragma unroll
            for (int r = 0; r < RM; r++) {
                float lo, hi; unpack2(acc[r][i], lo, hi);
                h2[r][i] = tanh_fast(lo + hi);
            }
        __syncthreads();  // [C] all h1 readers done
        #pragma unroll
        for (int i = 0; i < RN; i++) {
            if (vh[i]) {
                #pragma unroll
                for (int r = 0; r < RM; r++)
                    sts_f32(ABH + r * 400 + colh[i] * 4, h2[r][i]);
            }
        }
        __syncthreads();  // [D] h2 visible

        // ===== Layer 3 + Euler: x += (h2 @ W3^T + b3 - x0) * dt =====
        #pragma unroll
        for (int i = 0; i < RN; i++) {
            u64t b2 = pack2(lds_f32(W3_U + wofq[i] + K_B3 * 4), 0.0f);
            #pragma unroll
            for (int r = 0; r < RM; r++) acc[r][i] = b2;
        }
        gemm_tile(ABH, W3_U, wofq, acc);
        #pragma unroll
        for (int i = 0; i < RN; i++) {
            if (vq[i]) {
                int q = colq[i];
                float nz[RM];
                #pragma unroll
                for (int r = 0; r < RM; r++)
                    nz[r] = (q < QNUM) ? __ldg(&series[(rb[r] * QNUM + q) * CNUM + rc[r]])
                                       : __ldg(&rand_error[rb[r] * CNUM + rc[r]]);
                #pragma unroll
                for (int r = 0; r < RM; r++) {
                    u32t addr = ABX + r * 400 + q * 4;
                    float lo, hi; unpack2(acc[r][i], lo, hi);
                    float x = lds_f32(addr);
                    x = fmaf((lo + hi) - nz[r], dt, x);
                    sts_f32(addr, x);
                }
            }
        }
        // next iteration's [A] protects Xs
    }

    __syncthreads();
    // ---- write result (B, 97, C) ----
    for (int idx = tid; idx < QP1 * MT; idx += NTHREADS) {
        int q = idx / MT, m = idx - q * MT;
        int row = base + m;
        int b = row >> 4, c = row & 15;
        out[(b * QP1 + q) * CNUM + c] = Xs[XROWF(m) + q];
    }
}

extern "C" void kernel_launch(void* const* d_in, const int* in_sizes, int n_in,
                              void* d_out, int out_size)
{
    const float* series     = (const float*)d_in[0];
    const float* rand_error = (const float*)d_in[1];
    const float* W1 = (const float*)d_in[2];
    const float* b1 = (const float*)d_in[3];
    const float* W2 = (const float*)d_in[4];
    const float* b2 = (const float*)d_in[5];
    const float* W3 = (const float*)d_in[6];
    const float* b3 = (const float*)d_in[7];
    float* out = (float*)d_out;

    cudaFuncSetAttribute(arima_flow_kernel,
                         cudaFuncAttributeMaxDynamicSharedMemorySize, SMEM_BYTES);
    arima_flow_kernel<<<ROWS / MT, NTHREADS, SMEM_BYTES>>>(
        series, rand_error, W1, b1, W2, b2, W3, b3, out);
}

// round 10
// speedup vs baseline: 2.7423x; 2.7423x over previous
#include <cuda_runtime.h>
#include <cuda_bf16.h>
#include <cstdint>

typedef unsigned int u32t;

#define BNUM 1024
#define QNUM 96
#define CNUM 16
#define HNUM 100
#define NSTEPS_K 100
#define QP1 97
#define ROWS (BNUM*CNUM)
#define MT 112
#define GRID 147
#define NWARP 7
#define NTHREADS (NWARP*32)

#define NP 104            // padded N and K (6*16 + 8)
#define SWB 208           // row stride bytes (104 bf16) = 52 words (conflict-free)
#define NT 13             // n8 tiles
#define ROW8 (8*SWB)      // 1664

// SMEM byte layout
#define OFF_AHI 0
#define OFF_ALO (128*SWB)            // 26624
#define OFF_W   (2*128*SWB)          // 53248
#define WBUF    (104*SWB)            // 21632  (order: W1hi W1lo W2hi W2lo W3hi W3lo)
#define OFF_BIAS (OFF_W + 6*WBUF)    // 183040 ; bias[l][104] fp32, l=0..2
#define SMEM_TOTAL (OFF_BIAS + 3*104*4 + 64)   // 184352

extern __shared__ char smbase[];

__device__ __forceinline__ u32t smem_u32(const void* p) {
    u32t a;
    asm("{ .reg .u64 t; cvta.to.shared.u64 t, %1; cvt.u32.u64 %0, t; }" : "=r"(a) : "l"(p));
    return a;
}
__device__ __forceinline__ float tanh_fast(float x) {
    asm("tanh.approx.f32 %0, %0;" : "+f"(x));
    return x;
}
__device__ __forceinline__ u32t ldsw(u32t a) {
    u32t v; asm("ld.shared.b32 %0, [%1];" : "=r"(v) : "r"(a)); return v;
}
__device__ __forceinline__ float ldsf(u32t a) {
    float v; asm("ld.shared.f32 %0, [%1];" : "=f"(v) : "r"(a)); return v;
}
__device__ __forceinline__ void stsw(u32t a, u32t v) {
    asm volatile("st.shared.b32 [%0], %1;" :: "r"(a), "r"(v));
}
// pack (v0 -> low bf16, v1 -> high bf16) and the bf16 residual pair
__device__ __forceinline__ void split2(float v0, float v1, u32t& hi, u32t& lo) {
    asm("cvt.rn.bf16x2.f32 %0, %1, %2;" : "=r"(hi) : "f"(v1), "f"(v0));
    float h0 = __uint_as_float(hi << 16);
    float h1 = __uint_as_float(hi & 0xFFFF0000u);
    float l0 = v0 - h0, l1 = v1 - h1;
    asm("cvt.rn.bf16x2.f32 %0, %1, %2;" : "=r"(lo) : "f"(l1), "f"(l0));
}
__device__ __forceinline__ void mma16(float (&d)[4], u32t a0, u32t a1, u32t a2, u32t a3,
                                      u32t b0, u32t b1) {
    asm volatile("mma.sync.aligned.m16n8k16.row.col.f32.bf16.bf16.f32 "
        "{%0,%1,%2,%3}, {%4,%5,%6,%7}, {%8,%9}, {%0,%1,%2,%3};"
        : "+f"(d[0]), "+f"(d[1]), "+f"(d[2]), "+f"(d[3])
        : "r"(a0), "r"(a1), "r"(a2), "r"(a3), "r"(b0), "r"(b1));
}
__device__ __forceinline__ void mma8(float (&d)[4], u32t a0, u32t a1, u32t b0) {
    asm volatile("mma.sync.aligned.m16n8k8.row.col.f32.bf16.bf16.f32 "
        "{%0,%1,%2,%3}, {%4,%5}, {%6}, {%0,%1,%2,%3};"
        : "+f"(d[0]), "+f"(d[1]), "+f"(d[2]), "+f"(d[3])
        : "r"(a0), "r"(a1), "r"(b0));
}

__global__ __launch_bounds__(NTHREADS, 1)
void arima_mma_kernel(const float* __restrict__ series,
                      const float* __restrict__ rand_error,
                      const float* __restrict__ W1, const float* __restrict__ b1,
                      const float* __restrict__ W2, const float* __restrict__ b2,
                      const float* __restrict__ W3, const float* __restrict__ b3,
                      float* __restrict__ out)
{
    const u32t sb = smem_u32(smbase);
    const int tid  = threadIdx.x;
    const int w    = tid >> 5;
    const int lane = tid & 31;
    const int l4   = lane & 3;       // fragment col-pair / k-pair selector
    const int lr   = lane >> 2;      // fragment row selector (0..7)
    const int base = blockIdx.x * MT;
    const int r0   = w * 16 + lr;    // this thread's fragment row (0..111)
    const float dt = 1.0f / (float)NSTEPS_K;

    // ---- zero smem ----
    for (int i = tid; i < SMEM_TOTAL / 4; i += NTHREADS)
        ((u32t*)smbase)[i] = 0u;
    __syncthreads();

    // ---- weights -> SMEM bf16 hi/lo, row-major [j][k], stride 104 ----
    char* Wp = smbase + OFF_W;
    // W1: j<100, k<98 (k=97 is the t column)
    for (int idx = tid; idx < HNUM * (QNUM + 2); idx += NTHREADS) {
        int j = idx / (QNUM + 2), k = idx - j * (QNUM + 2);
        float v = W1[idx];
        __nv_bfloat16 h = __float2bfloat16(v);
        __nv_bfloat16 l = __float2bfloat16(v - __bfloat162float(h));
        u32t o = (u32t)(j * SWB + k * 2);
        *(__nv_bfloat16*)(Wp + 0 * WBUF + o) = h;
        *(__nv_bfloat16*)(Wp + 1 * WBUF + o) = l;
    }
    // W2: 100x100
    for (int idx = tid; idx < HNUM * HNUM; idx += NTHREADS) {
        int j = idx / HNUM, k = idx - j * HNUM;
        float v = W2[idx];
        __nv_bfloat16 h = __float2bfloat16(v);
        __nv_bfloat16 l = __float2bfloat16(v - __bfloat162float(h));
        u32t o = (u32t)(j * SWB + k * 2);
        *(__nv_bfloat16*)(Wp + 2 * WBUF + o) = h;
        *(__nv_bfloat16*)(Wp + 3 * WBUF + o) = l;
    }
    // W3: j<97, k<100
    for (int idx = tid; idx < QP1 * HNUM; idx += NTHREADS) {
        int j = idx / HNUM, k = idx - j * HNUM;
        float v = W3[idx];
        __nv_bfloat16 h = __float2bfloat16(v);
        __nv_bfloat16 l = __float2bfloat16(v - __bfloat162float(h));
        u32t o = (u32t)(j * SWB + k * 2);
        *(__nv_bfloat16*)(Wp + 4 * WBUF + o) = h;
        *(__nv_bfloat16*)(Wp + 5 * WBUF + o) = l;
    }
    float* biasp = (float*)(smbase + OFF_BIAS);
    for (int j = tid; j < HNUM; j += NTHREADS) {
        biasp[j]       = b1[j];
        biasp[104 + j] = b2[j];
    }
    for (int j = tid; j < QP1; j += NTHREADS) biasp[208 + j] = b3[j];

    // ---- per-thread global row helpers ----
    const int grow0 = base + r0, grow1 = grow0 + 8;
    const bool gv0 = grow0 < ROWS, gv1 = grow1 < ROWS;
    const int gb0 = grow0 >> 4, gc0 = grow0 & 15;
    const int gb1 = grow1 >> 4, gc1 = grow1 & 15;
    const float* ps0 = series + (size_t)gb0 * (QNUM * CNUM) + gc0;
    const float* ps1 = series + (size_t)gb1 * (QNUM * CNUM) + gc1;
    const float* pr0 = rand_error + (size_t)gb0 * CNUM + gc0;
    const float* pr1 = rand_error + (size_t)gb1 * CNUM + gc1;

    // ---- x0 into D-fragment registers ----
    float x[NT][4];
    #pragma unroll
    for (int n = 0; n < NT; n++) {
        int q0 = n * 8 + l4 * 2, q1 = q0 + 1;
        x[n][0] = (gv0 && q0 < QNUM) ? __ldg(ps0 + q0 * CNUM) : (gv0 && q0 == QNUM) ? __ldg(pr0) : 0.0f;
        x[n][1] = (gv0 && q1 < QNUM) ? __ldg(ps0 + q1 * CNUM) : (gv0 && q1 == QNUM) ? __ldg(pr0) : 0.0f;
        x[n][2] = (gv1 && q0 < QNUM) ? __ldg(ps1 + q0 * CNUM) : (gv1 && q0 == QNUM) ? __ldg(pr1) : 0.0f;
        x[n][3] = (gv1 && q1 < QNUM) ? __ldg(ps1 + q1 * CNUM) : (gv1 && q1 == QNUM) ? __ldg(pr1) : 0.0f;
    }

    // store x -> A (bf16 hi/lo), injecting t at col 97.
    // D fragment col pair = n*8 + l4*2 -> byte offset n*16 + l4*4 (FIX: was l4*8)
    const u32t abw = (u32t)(r0 * SWB + l4 * 4);
    auto store_xA = [&](float tn) {
        #pragma unroll
        for (int n = 0; n < NT; n++) {
            float v0 = x[n][0], v1 = x[n][1], v2 = x[n][2], v3 = x[n][3];
            if (n == 12 && l4 == 0) { v1 = tn; v3 = tn; }   // col 97 = t
            u32t bo = abw + (u32t)(n * 16);
            u32t hw, lw;
            split2(v0, v1, hw, lw);
            stsw(sb + OFF_AHI + bo, hw);
            stsw(sb + OFF_ALO + bo, lw);
            split2(v2, v3, hw, lw);
            stsw(sb + OFF_AHI + bo + ROW8, hw);
            stsw(sb + OFF_ALO + bo + ROW8, lw);
        }
    };
    store_xA(0.0f);
    __syncthreads();  // weights + all initial A slabs visible

    const u32t aHb = sb + OFF_AHI + (u32t)(r0 * SWB + l4 * 4);
    const u32t aLb = aHb + (u32t)(OFF_ALO - OFF_AHI);
    const u32t wJ  = (u32t)(lr * SWB + l4 * 4);

    for (int s = 0; s < NSTEPS_K; s++) {
        #pragma unroll 1
        for (int l = 0; l < 3; l++) {
            float acc[NT][4];
            #pragma unroll
            for (int n = 0; n < NT; n++)
                #pragma unroll
                for (int e = 0; e < 4; e++) acc[n][e] = 0.0f;

            const u32t wHb = sb + OFF_W + (u32t)l * (2 * WBUF) + wJ;
            const u32t wLb = wHb + WBUF;

            #pragma unroll 1
            for (int kc = 0; kc < 6; kc++) {
                u32t ko = (u32t)(kc * 32);
                u32t h0 = ldsw(aHb + ko), h1 = ldsw(aHb + ko + ROW8);
                u32t h2 = ldsw(aHb + ko + 16), h3 = ldsw(aHb + ko + ROW8 + 16);
                u32t g0 = ldsw(aLb + ko), g1 = ldsw(aLb + ko + ROW8);
                u32t g2 = ldsw(aLb + ko + 16), g3 = ldsw(aLb + ko + ROW8 + 16);
                #pragma unroll
                for (int n = 0; n < NT; n++) {
                    u32t wo = ko + (u32t)(n * ROW8);
                    u32t bh0 = ldsw(wHb + wo), bh1 = ldsw(wHb + wo + 16);
                    u32t bl0 = ldsw(wLb + wo), bl1 = ldsw(wLb + wo + 16);
                    mma16(acc[n], h0, h1, h2, h3, bh0, bh1);
                    mma16(acc[n], h0, h1, h2, h3, bl0, bl1);
                    mma16(acc[n], g0, g1, g2, g3, bh0, bh1);
                }
            }
            {   // k8 tail: k = 96..103
                u32t ko = 192;
                u32t h0 = ldsw(aHb + ko), h1 = ldsw(aHb + ko + ROW8);
                u32t g0 = ldsw(aLb + ko), g1 = ldsw(aLb + ko + ROW8);
                #pragma unroll
                for (int n = 0; n < NT; n++) {
                    u32t wo = ko + (u32t)(n * ROW8);
                    u32t bh0 = ldsw(wHb + wo);
                    u32t bl0 = ldsw(wLb + wo);
                    mma8(acc[n], h0, h1, bh0);
                    mma8(acc[n], h0, h1, bl0);
                    mma8(acc[n], g0, g1, bh0);
                }
            }
            __syncwarp();  // all lanes done reading A before epilogue overwrites

            if (l < 2) {
                // ===== hidden epilogue: A <- tanh(acc + bias) =====
                const u32t bp = sb + OFF_BIAS + (u32t)(l * 416 + l4 * 8);
                #pragma unroll
                for (int n = 0; n < NT; n++) {
                    float bb0 = ldsf(bp + (u32t)(n * 32));
                    float bb1 = ldsf(bp + (u32t)(n * 32) + 4);
                    float v0 = tanh_fast(acc[n][0] + bb0);
                    float v1 = tanh_fast(acc[n][1] + bb1);
                    float v2 = tanh_fast(acc[n][2] + bb0);
                    float v3 = tanh_fast(acc[n][3] + bb1);
                    u32t bo = abw + (u32t)(n * 16);
                    u32t hw, lw;
                    split2(v0, v1, hw, lw);
                    stsw(sb + OFF_AHI + bo, hw);
                    stsw(sb + OFF_ALO + bo, lw);
                    split2(v2, v3, hw, lw);
                    stsw(sb + OFF_AHI + bo + ROW8, hw);
                    stsw(sb + OFF_ALO + bo + ROW8, lw);
                }
            } else {
                // ===== Euler epilogue: x += (acc + b3 - noise)*dt; A <- x, t_next =====
                const u32t bp3 = sb + OFF_BIAS + (u32t)(2 * 416 + l4 * 8);
                #pragma unroll
                for (int n = 0; n < NT; n++) {
                    float bb0 = ldsf(bp3 + (u32t)(n * 32));
                    float bb1 = ldsf(bp3 + (u32t)(n * 32) + 4);
                    float nz0, nz1, nz2, nz3;
                    if (n < 12) {
                        int q0 = n * 8 + l4 * 2, q1 = q0 + 1;   // < 96
                        nz0 = gv0 ? __ldg(ps0 + q0 * CNUM) : 0.0f;
                        nz1 = gv0 ? __ldg(ps0 + q1 * CNUM) : 0.0f;
                        nz2 = gv1 ? __ldg(ps1 + q0 * CNUM) : 0.0f;
                        nz3 = gv1 ? __ldg(ps1 + q1 * CNUM) : 0.0f;
                    } else {
                        nz0 = (l4 == 0 && gv0) ? __ldg(pr0) : 0.0f;  // col 96
                        nz1 = 0.0f;
                        nz2 = (l4 == 0 && gv1) ? __ldg(pr1) : 0.0f;
                        nz3 = 0.0f;
                    }
                    x[n][0] = fmaf((acc[n][0] + bb0) - nz0, dt, x[n][0]);
                    x[n][1] = fmaf((acc[n][1] + bb1) - nz1, dt, x[n][1]);
                    x[n][2] = fmaf((acc[n][2] + bb0) - nz2, dt, x[n][2]);
                    x[n][3] = fmaf((acc[n][3] + bb1) - nz3, dt, x[n][3]);
                }
                store_xA((float)(s + 1) * dt);
            }
            __syncwarp();  // stores visible to next layer's fragment loads
        }
    }

    // ---- write result (B, 97, C) from x registers ----
    #pragma unroll
    for (int n = 0; n < NT; n++) {
        int q0 = n * 8 + l4 * 2, q1 = q0 + 1;
        if (gv0 && q0 < QP1) out[((size_t)gb0 * QP1 + q0) * CNUM + gc0] = x[n][0];
        if (gv0 && q1 < QP1) out[((size_t)gb0 * QP1 + q1) * CNUM + gc0] = x[n][1];
        if (gv1 && q0 < QP1) out[((size_t)gb1 * QP1 + q0) * CNUM + gc1] = x[n][2];
        if (gv1 && q1 < QP1) out[((size_t)gb1 * QP1 + q1) * CNUM + gc1] = x[n][3];
    }
}

extern "C" void kernel_launch(void* const* d_in, const int* in_sizes, int n_in,
                              void* d_out, int out_size)
{
    const float* series     = (const float*)d_in[0];
    const float* rand_error = (const float*)d_in[1];
    const float* W1 = (const float*)d_in[2];
    const float* b1 = (const float*)d_in[3];
    const float* W2 = (const float*)d_in[4];
    const float* b2 = (const float*)d_in[5];
    const float* W3 = (const float*)d_in[6];
    const float* b3 = (const float*)d_in[7];
    float* out = (float*)d_out;

    cudaFuncSetAttribute(arima_mma_kernel,
                         cudaFuncAttributeMaxDynamicSharedMemorySize, SMEM_TOTAL);
    arima_mma_kernel<<<GRID, NTHREADS, SMEM_TOTAL>>>(
        series, rand_error, W1, b1, W2, b2, W3, b3, out);
}